// round 2
// baseline (speedup 1.0000x reference)
#include <cuda_runtime.h>
#include <math.h>

#define Bc   8
#define Lc   96
#define Hc   8
#define Ec   64
#define EHc  128
#define ROWS 64          // B*H
#define NT   256

#define YPITCH 65        // padded state row pitch (bank-conflict avoidance)
#define HPITCH 130       // padded hidden row pitch (even -> float2 aligned)

// ---- shared memory layout (in floats) ----
constexpr int SM_W1  = 0;                       // [64][128]
constexpr int SM_W2  = SM_W1 + Ec * EHc;        // [128][64]
constexpr int SM_B1  = SM_W2 + EHc * Ec;        // [128]
constexpr int SM_B2  = SM_B1 + EHc;             // [64]
constexpr int SM_TS  = SM_B2 + Ec;              // [96]
constexpr int SM_Y   = SM_TS + Lc;              // [64][65]
constexpr int SM_YIN = SM_Y   + ROWS * YPITCH;  // [64][65]
constexpr int SM_K1  = SM_YIN + ROWS * YPITCH;  // [64][65]  (becomes ACC at stage 2)
constexpr int SM_K2  = SM_K1  + ROWS * YPITCH;  // [64][65]
constexpr int SM_HS  = SM_K2  + ROWS * YPITCH;  // [64][130]
constexpr int SM_TOT = SM_HS  + ROWS * HPITCH;
constexpr int SMEM_BYTES = SM_TOT * 4;          // ~166.5 KB

// ---- packed fp32x2 helpers (sm_103a) ----
__device__ __forceinline__ unsigned long long pk2(float a, float b) {
    unsigned long long r;
    asm("mov.b64 %0, {%1, %2};" : "=l"(r) : "f"(a), "f"(b));
    return r;
}
__device__ __forceinline__ void upk2(unsigned long long v, float& a, float& b) {
    asm("mov.b64 {%0, %1}, %2;" : "=f"(a), "=f"(b) : "l"(v));
}
__device__ __forceinline__ unsigned long long f2fma(unsigned long long a,
                                                    unsigned long long b,
                                                    unsigned long long c) {
    unsigned long long d;
    asm("fma.rn.f32x2 %0, %1, %2, %3;" : "=l"(d) : "l"(a), "l"(b), "l"(c));
    return d;
}

// GEMM1: Hs = tanh(Yin @ W1 + b1).  Thread (rg, c): rows rg*4+i, cols j = 2c+{0,1}+32m.
__device__ __forceinline__ void mlp_gemm1(float* sm, const float* __restrict__ Yin,
                                          int rg, int c) {
    const float* W1 = sm + SM_W1;
    const float* b1 = sm + SM_B1;
    float* Hs = sm + SM_HS;

    unsigned long long acc[4][4];
#pragma unroll
    for (int m = 0; m < 4; ++m) {
        float2 bv = *(const float2*)&b1[c * 2 + 32 * m];
        unsigned long long bb = pk2(bv.x, bv.y);
#pragma unroll
        for (int i = 0; i < 4; ++i) acc[i][m] = bb;
    }

#pragma unroll 4
    for (int e = 0; e < Ec; ++e) {
        unsigned long long y[4];
#pragma unroll
        for (int i = 0; i < 4; ++i) {
            float v = Yin[(rg * 4 + i) * YPITCH + e];
            y[i] = pk2(v, v);
        }
#pragma unroll
        for (int m = 0; m < 4; ++m) {
            unsigned long long w =
                *(const unsigned long long*)&W1[e * EHc + c * 2 + 32 * m];
#pragma unroll
            for (int i = 0; i < 4; ++i) acc[i][m] = f2fma(y[i], w, acc[i][m]);
        }
    }

#pragma unroll
    for (int i = 0; i < 4; ++i) {
#pragma unroll
        for (int m = 0; m < 4; ++m) {
            float a, b;
            upk2(acc[i][m], a, b);
            float2 t;
            t.x = tanhf(a);
            t.y = tanhf(b);
            *(float2*)&Hs[(rg * 4 + i) * HPITCH + c * 2 + 32 * m] = t;
        }
    }
}

// GEMM2 + stage epilogue.  Thread (rg, c): rows rg*4+i, cols e = 2c+{0,1}+32m (m<2).
// ST=0: K1=k1; Yin = Y + dt/3*k1
// ST=1: K2=k2; Yin = Y + dt*k2 - dt/3*K1
// ST=2: ACC(K1) = K1 + 3*(K2 + k3); Yin = Y + dt*(K1 - K2 + k3)
// ST=3: Y += dt/8*(ACC + k4); emit output {x0, y}
template <int ST>
__device__ __forceinline__ void mlp_gemm2_epi(float* sm, int rg, int c, float dt,
                                              const float2 x0v[4][2],
                                              const int obase[4][2],
                                              float* __restrict__ outj) {
    const float* W2 = sm + SM_W2;
    const float* b2 = sm + SM_B2;
    const float* Hs = sm + SM_HS;
    float* Y   = sm + SM_Y;
    float* Yin = sm + SM_YIN;
    float* K1  = sm + SM_K1;
    float* K2  = sm + SM_K2;

    unsigned long long acc[4][2];
#pragma unroll
    for (int m = 0; m < 2; ++m) {
        float2 bv = *(const float2*)&b2[c * 2 + 32 * m];
        unsigned long long bb = pk2(bv.x, bv.y);
#pragma unroll
        for (int i = 0; i < 4; ++i) acc[i][m] = bb;
    }

#pragma unroll 2
    for (int j = 0; j < EHc; j += 2) {
        unsigned long long h0[4], h1[4];
#pragma unroll
        for (int i = 0; i < 4; ++i) {
            float2 hv = *(const float2*)&Hs[(rg * 4 + i) * HPITCH + j];
            h0[i] = pk2(hv.x, hv.x);
            h1[i] = pk2(hv.y, hv.y);
        }
#pragma unroll
        for (int m = 0; m < 2; ++m) {
            unsigned long long w0 =
                *(const unsigned long long*)&W2[j * Ec + c * 2 + 32 * m];
            unsigned long long w1 =
                *(const unsigned long long*)&W2[(j + 1) * Ec + c * 2 + 32 * m];
#pragma unroll
            for (int i = 0; i < 4; ++i) {
                acc[i][m] = f2fma(h0[i], w0, acc[i][m]);
                acc[i][m] = f2fma(h1[i], w1, acc[i][m]);
            }
        }
    }

    const float dt3 = dt * (1.0f / 3.0f);
    const float dt8 = dt * 0.125f;
#pragma unroll
    for (int i = 0; i < 4; ++i) {
        int r = rg * 4 + i;
#pragma unroll
        for (int m = 0; m < 2; ++m) {
            int e = c * 2 + 32 * m;
            int off = r * YPITCH + e;
            float o0, o1;
            upk2(acc[i][m], o0, o1);
            if (ST == 0) {
                K1[off] = o0;
                K1[off + 1] = o1;
                Yin[off]     = Y[off]     + dt3 * o0;
                Yin[off + 1] = Y[off + 1] + dt3 * o1;
            } else if (ST == 1) {
                K2[off] = o0;
                K2[off + 1] = o1;
                Yin[off]     = Y[off]     + dt * o0 - dt3 * K1[off];
                Yin[off + 1] = Y[off + 1] + dt * o1 - dt3 * K1[off + 1];
            } else if (ST == 2) {
                float k1a = K1[off], k1b = K1[off + 1];
                float k2a = K2[off], k2b = K2[off + 1];
                K1[off]     = k1a + 3.0f * (k2a + o0);
                K1[off + 1] = k1b + 3.0f * (k2b + o1);
                Yin[off]     = Y[off]     + dt * (k1a - k2a + o0);
                Yin[off + 1] = Y[off + 1] + dt * (k1b - k2b + o1);
            } else {
                float yn0 = Y[off]     + dt8 * (K1[off] + o0);
                float yn1 = Y[off + 1] + dt8 * (K1[off + 1] + o1);
                Y[off] = yn0;
                Y[off + 1] = yn1;
                float4 v = make_float4(x0v[i][m].x, yn0, x0v[i][m].y, yn1);
                *(float4*)&outj[obase[i][m]] = v;
            }
        }
    }
}

__device__ __forceinline__ void rk4_step(float* sm, int rg, int c, float dt,
                                         const float2 x0v[4][2],
                                         const int obase[4][2],
                                         float* __restrict__ outj) {
    mlp_gemm1(sm, sm + SM_Y, rg, c);
    __syncthreads();
    mlp_gemm2_epi<0>(sm, rg, c, dt, x0v, obase, outj);
    __syncthreads();
    mlp_gemm1(sm, sm + SM_YIN, rg, c);
    __syncthreads();
    mlp_gemm2_epi<1>(sm, rg, c, dt, x0v, obase, outj);
    __syncthreads();
    mlp_gemm1(sm, sm + SM_YIN, rg, c);
    __syncthreads();
    mlp_gemm2_epi<2>(sm, rg, c, dt, x0v, obase, outj);
    __syncthreads();
    mlp_gemm1(sm, sm + SM_YIN, rg, c);
    __syncthreads();
    mlp_gemm2_epi<3>(sm, rg, c, dt, x0v, obase, outj);
    __syncthreads();
}

__global__ void __launch_bounds__(NT)
ode_kernel(const float* __restrict__ x, const float* __restrict__ tsg,
           const float* __restrict__ W1g, const float* __restrict__ b1g,
           const float* __restrict__ W2g, const float* __restrict__ b2g,
           float* __restrict__ out) {
    extern __shared__ float sm[];
    const int tid = threadIdx.x;
    const int idx = blockIdx.x;
    const int c  = tid & 15;
    const int rg = tid >> 4;

    // stage weights
    for (int i = tid; i < Ec * EHc; i += NT) sm[SM_W1 + i] = W1g[i];
    for (int i = tid; i < EHc * Ec; i += NT) sm[SM_W2 + i] = W2g[i];
    if (tid < EHc) sm[SM_B1 + tid] = b1g[tid];
    if (tid < Ec)  sm[SM_B2 + tid] = b2g[tid];
    if (tid < Lc)  sm[SM_TS + tid] = tsg[tid];

    // per-thread x0 registers + output base offsets (element ownership = GEMM2 tile)
    float2 x0v[4][2];
    int obase[4][2];
#pragma unroll
    for (int i = 0; i < 4; ++i) {
        int r = rg * 4 + i, b = r >> 3, h = r & 7;
#pragma unroll
        for (int m = 0; m < 2; ++m) {
            int e = c * 2 + 32 * m;
            x0v[i][m] = *(const float2*)&x[b * (Lc * Hc * Ec) + idx * (Hc * Ec) +
                                           h * Ec + e];
            obase[i][m] = b * (Lc * Lc * Hc * Ec * 2) + idx * (Lc * Hc * Ec * 2) +
                          h * (Ec * 2) + e * 2;
        }
    }

    float* Y = sm + SM_Y;
    // initial state + emission at j = idx (state == x0)
#pragma unroll
    for (int i = 0; i < 4; ++i) {
#pragma unroll
        for (int m = 0; m < 2; ++m) {
            int r = rg * 4 + i, e = c * 2 + 32 * m;
            Y[r * YPITCH + e]     = x0v[i][m].x;
            Y[r * YPITCH + e + 1] = x0v[i][m].y;
            float4 v = make_float4(x0v[i][m].x, x0v[i][m].x, x0v[i][m].y, x0v[i][m].y);
            *(float4*)&out[obase[i][m] + idx * (Hc * Ec * 2)] = v;
        }
    }
    __syncthreads();

    const float* ts = sm + SM_TS;

    // forward: steps s = idx .. L-2, emit at j = s+1
    for (int s = idx; s < Lc - 1; ++s) {
        float dt = ts[s + 1] - ts[s];
        rk4_step(sm, rg, c, dt, x0v, obase, out + (s + 1) * (Hc * Ec * 2));
    }

    __syncthreads();
    // reset state for backward pass
#pragma unroll
    for (int i = 0; i < 4; ++i) {
#pragma unroll
        for (int m = 0; m < 2; ++m) {
            int r = rg * 4 + i, e = c * 2 + 32 * m;
            Y[r * YPITCH + e]     = x0v[i][m].x;
            Y[r * YPITCH + e + 1] = x0v[i][m].y;
        }
    }
    __syncthreads();

    // backward: steps s = idx .. 1 (dt negative), emit at j = s-1
    for (int s = idx; s >= 1; --s) {
        float dt = ts[s - 1] - ts[s];
        rk4_step(sm, rg, c, dt, x0v, obase, out + (s - 1) * (Hc * Ec * 2));
    }
}

extern "C" void kernel_launch(void* const* d_in, const int* in_sizes, int n_in,
                              void* d_out, int out_size) {
    const float* x   = (const float*)d_in[0];
    const float* ts  = (const float*)d_in[1];
    const float* W1  = (const float*)d_in[2];
    const float* b1  = (const float*)d_in[3];
    const float* W2  = (const float*)d_in[4];
    const float* b2  = (const float*)d_in[5];
    float* out = (float*)d_out;

    cudaFuncSetAttribute(ode_kernel, cudaFuncAttributeMaxDynamicSharedMemorySize,
                         SMEM_BYTES);
    ode_kernel<<<Lc, NT, SMEM_BYTES>>>(x, ts, W1, b1, W2, b2, out);
}

// round 3
// speedup vs baseline: 1.0000x; 1.0000x over previous
#include <cuda_runtime.h>
#include <math.h>

#define Bc   8
#define Lc   96
#define Hc   8
#define Ec   64
#define EHc  128
#define ROWS 64          // B*H
#define NT   256

#define YPITCH 65        // padded state row pitch (bank-conflict avoidance)
#define HPITCH 130       // padded hidden row pitch (even -> float2 aligned)

// ---- shared memory layout (in floats) ----
constexpr int SM_W1  = 0;                       // [64][128]
constexpr int SM_W2  = SM_W1 + Ec * EHc;        // [128][64]
constexpr int SM_B1  = SM_W2 + EHc * Ec;        // [128]
constexpr int SM_B2  = SM_B1 + EHc;             // [64]
constexpr int SM_TS  = SM_B2 + Ec;              // [96]
constexpr int SM_Y   = SM_TS + Lc;              // [64][65]
constexpr int SM_YIN = SM_Y   + ROWS * YPITCH;  // [64][65]
constexpr int SM_K1  = SM_YIN + ROWS * YPITCH;  // [64][65]  (becomes ACC at stage 2)
constexpr int SM_K2  = SM_K1  + ROWS * YPITCH;  // [64][65]
constexpr int SM_HS  = SM_K2  + ROWS * YPITCH;  // [64][130]
constexpr int SM_TOT = SM_HS  + ROWS * HPITCH;
constexpr int SMEM_BYTES = SM_TOT * 4;          // ~166.5 KB

// ---- packed fp32x2 helpers (sm_103a) ----
__device__ __forceinline__ unsigned long long pk2(float a, float b) {
    unsigned long long r;
    asm("mov.b64 %0, {%1, %2};" : "=l"(r) : "f"(a), "f"(b));
    return r;
}
__device__ __forceinline__ void upk2(unsigned long long v, float& a, float& b) {
    asm("mov.b64 {%0, %1}, %2;" : "=f"(a), "=f"(b) : "l"(v));
}
__device__ __forceinline__ unsigned long long f2fma(unsigned long long a,
                                                    unsigned long long b,
                                                    unsigned long long c) {
    unsigned long long d;
    asm("fma.rn.f32x2 %0, %1, %2, %3;" : "=l"(d) : "l"(a), "l"(b), "l"(c));
    return d;
}

// GEMM1: Hs = tanh(Yin @ W1 + b1).  Thread (rg, c): rows rg*4+i, cols j = 2c+{0,1}+32m.
__device__ __forceinline__ void mlp_gemm1(float* sm, const float* __restrict__ Yin,
                                          int rg, int c) {
    const float* W1 = sm + SM_W1;
    const float* b1 = sm + SM_B1;
    float* Hs = sm + SM_HS;

    unsigned long long acc[4][4];
#pragma unroll
    for (int m = 0; m < 4; ++m) {
        float2 bv = *(const float2*)&b1[c * 2 + 32 * m];
        unsigned long long bb = pk2(bv.x, bv.y);
#pragma unroll
        for (int i = 0; i < 4; ++i) acc[i][m] = bb;
    }

#pragma unroll 4
    for (int e = 0; e < Ec; ++e) {
        unsigned long long y[4];
#pragma unroll
        for (int i = 0; i < 4; ++i) {
            float v = Yin[(rg * 4 + i) * YPITCH + e];
            y[i] = pk2(v, v);
        }
#pragma unroll
        for (int m = 0; m < 4; ++m) {
            unsigned long long w =
                *(const unsigned long long*)&W1[e * EHc + c * 2 + 32 * m];
#pragma unroll
            for (int i = 0; i < 4; ++i) acc[i][m] = f2fma(y[i], w, acc[i][m]);
        }
    }

#pragma unroll
    for (int i = 0; i < 4; ++i) {
#pragma unroll
        for (int m = 0; m < 4; ++m) {
            float a, b;
            upk2(acc[i][m], a, b);
            float2 t;
            t.x = tanhf(a);
            t.y = tanhf(b);
            *(float2*)&Hs[(rg * 4 + i) * HPITCH + c * 2 + 32 * m] = t;
        }
    }
}

// GEMM2 + stage epilogue.  Thread (rg, c): rows rg*4+i, cols e = 2c+{0,1}+32m (m<2).
// ST=0: K1=k1; Yin = Y + dt/3*k1
// ST=1: K2=k2; Yin = Y + dt*k2 - dt/3*K1
// ST=2: ACC(K1) = K1 + 3*(K2 + k3); Yin = Y + dt*(K1 - K2 + k3)
// ST=3: Y += dt/8*(ACC + k4); emit output {x0, y}
template <int ST>
__device__ __forceinline__ void mlp_gemm2_epi(float* sm, int rg, int c, float dt,
                                              const float2 x0v[4][2],
                                              const int obase[4][2],
                                              float* __restrict__ outj) {
    const float* W2 = sm + SM_W2;
    const float* b2 = sm + SM_B2;
    const float* Hs = sm + SM_HS;
    float* Y   = sm + SM_Y;
    float* Yin = sm + SM_YIN;
    float* K1  = sm + SM_K1;
    float* K2  = sm + SM_K2;

    unsigned long long acc[4][2];
#pragma unroll
    for (int m = 0; m < 2; ++m) {
        float2 bv = *(const float2*)&b2[c * 2 + 32 * m];
        unsigned long long bb = pk2(bv.x, bv.y);
#pragma unroll
        for (int i = 0; i < 4; ++i) acc[i][m] = bb;
    }

#pragma unroll 2
    for (int j = 0; j < EHc; j += 2) {
        unsigned long long h0[4], h1[4];
#pragma unroll
        for (int i = 0; i < 4; ++i) {
            float2 hv = *(const float2*)&Hs[(rg * 4 + i) * HPITCH + j];
            h0[i] = pk2(hv.x, hv.x);
            h1[i] = pk2(hv.y, hv.y);
        }
#pragma unroll
        for (int m = 0; m < 2; ++m) {
            unsigned long long w0 =
                *(const unsigned long long*)&W2[j * Ec + c * 2 + 32 * m];
            unsigned long long w1 =
                *(const unsigned long long*)&W2[(j + 1) * Ec + c * 2 + 32 * m];
#pragma unroll
            for (int i = 0; i < 4; ++i) {
                acc[i][m] = f2fma(h0[i], w0, acc[i][m]);
                acc[i][m] = f2fma(h1[i], w1, acc[i][m]);
            }
        }
    }

    const float dt3 = dt * (1.0f / 3.0f);
    const float dt8 = dt * 0.125f;
#pragma unroll
    for (int i = 0; i < 4; ++i) {
        int r = rg * 4 + i;
#pragma unroll
        for (int m = 0; m < 2; ++m) {
            int e = c * 2 + 32 * m;
            int off = r * YPITCH + e;
            float o0, o1;
            upk2(acc[i][m], o0, o1);
            if (ST == 0) {
                K1[off] = o0;
                K1[off + 1] = o1;
                Yin[off]     = Y[off]     + dt3 * o0;
                Yin[off + 1] = Y[off + 1] + dt3 * o1;
            } else if (ST == 1) {
                K2[off] = o0;
                K2[off + 1] = o1;
                Yin[off]     = Y[off]     + dt * o0 - dt3 * K1[off];
                Yin[off + 1] = Y[off + 1] + dt * o1 - dt3 * K1[off + 1];
            } else if (ST == 2) {
                float k1a = K1[off], k1b = K1[off + 1];
                float k2a = K2[off], k2b = K2[off + 1];
                K1[off]     = k1a + 3.0f * (k2a + o0);
                K1[off + 1] = k1b + 3.0f * (k2b + o1);
                Yin[off]     = Y[off]     + dt * (k1a - k2a + o0);
                Yin[off + 1] = Y[off + 1] + dt * (k1b - k2b + o1);
            } else {
                float yn0 = Y[off]     + dt8 * (K1[off] + o0);
                float yn1 = Y[off + 1] + dt8 * (K1[off + 1] + o1);
                Y[off] = yn0;
                Y[off + 1] = yn1;
                float4 v = make_float4(x0v[i][m].x, yn0, x0v[i][m].y, yn1);
                *(float4*)&outj[obase[i][m]] = v;
            }
        }
    }
}

__device__ __forceinline__ void rk4_step(float* sm, int rg, int c, float dt,
                                         const float2 x0v[4][2],
                                         const int obase[4][2],
                                         float* __restrict__ outj) {
    mlp_gemm1(sm, sm + SM_Y, rg, c);
    __syncthreads();
    mlp_gemm2_epi<0>(sm, rg, c, dt, x0v, obase, outj);
    __syncthreads();
    mlp_gemm1(sm, sm + SM_YIN, rg, c);
    __syncthreads();
    mlp_gemm2_epi<1>(sm, rg, c, dt, x0v, obase, outj);
    __syncthreads();
    mlp_gemm1(sm, sm + SM_YIN, rg, c);
    __syncthreads();
    mlp_gemm2_epi<2>(sm, rg, c, dt, x0v, obase, outj);
    __syncthreads();
    mlp_gemm1(sm, sm + SM_YIN, rg, c);
    __syncthreads();
    mlp_gemm2_epi<3>(sm, rg, c, dt, x0v, obase, outj);
    __syncthreads();
}

__global__ void __launch_bounds__(NT)
ode_kernel(const float* __restrict__ x, const float* __restrict__ tsg,
           const float* __restrict__ W1g, const float* __restrict__ b1g,
           const float* __restrict__ W2g, const float* __restrict__ b2g,
           float* __restrict__ out) {
    extern __shared__ float sm[];
    const int tid = threadIdx.x;
    const int idx = blockIdx.x;
    const int c  = tid & 15;
    const int rg = tid >> 4;

    // stage weights
    for (int i = tid; i < Ec * EHc; i += NT) sm[SM_W1 + i] = W1g[i];
    for (int i = tid; i < EHc * Ec; i += NT) sm[SM_W2 + i] = W2g[i];
    if (tid < EHc) sm[SM_B1 + tid] = b1g[tid];
    if (tid < Ec)  sm[SM_B2 + tid] = b2g[tid];
    if (tid < Lc)  sm[SM_TS + tid] = tsg[tid];

    // per-thread x0 registers + output base offsets (element ownership = GEMM2 tile)
    float2 x0v[4][2];
    int obase[4][2];
#pragma unroll
    for (int i = 0; i < 4; ++i) {
        int r = rg * 4 + i, b = r >> 3, h = r & 7;
#pragma unroll
        for (int m = 0; m < 2; ++m) {
            int e = c * 2 + 32 * m;
            x0v[i][m] = *(const float2*)&x[b * (Lc * Hc * Ec) + idx * (Hc * Ec) +
                                           h * Ec + e];
            obase[i][m] = b * (Lc * Lc * Hc * Ec * 2) + idx * (Lc * Hc * Ec * 2) +
                          h * (Ec * 2) + e * 2;
        }
    }

    float* Y = sm + SM_Y;
    // initial state + emission at j = idx (state == x0)
#pragma unroll
    for (int i = 0; i < 4; ++i) {
#pragma unroll
        for (int m = 0; m < 2; ++m) {
            int r = rg * 4 + i, e = c * 2 + 32 * m;
            Y[r * YPITCH + e]     = x0v[i][m].x;
            Y[r * YPITCH + e + 1] = x0v[i][m].y;
            float4 v = make_float4(x0v[i][m].x, x0v[i][m].x, x0v[i][m].y, x0v[i][m].y);
            *(float4*)&out[obase[i][m] + idx * (Hc * Ec * 2)] = v;
        }
    }
    __syncthreads();

    const float* ts = sm + SM_TS;

    // forward: steps s = idx .. L-2, emit at j = s+1
    for (int s = idx; s < Lc - 1; ++s) {
        float dt = ts[s + 1] - ts[s];
        rk4_step(sm, rg, c, dt, x0v, obase, out + (s + 1) * (Hc * Ec * 2));
    }

    __syncthreads();
    // reset state for backward pass
#pragma unroll
    for (int i = 0; i < 4; ++i) {
#pragma unroll
        for (int m = 0; m < 2; ++m) {
            int r = rg * 4 + i, e = c * 2 + 32 * m;
            Y[r * YPITCH + e]     = x0v[i][m].x;
            Y[r * YPITCH + e + 1] = x0v[i][m].y;
        }
    }
    __syncthreads();

    // backward: steps s = idx .. 1 (dt negative), emit at j = s-1
    for (int s = idx; s >= 1; --s) {
        float dt = ts[s - 1] - ts[s];
        rk4_step(sm, rg, c, dt, x0v, obase, out + (s - 1) * (Hc * Ec * 2));
    }
}

extern "C" void kernel_launch(void* const* d_in, const int* in_sizes, int n_in,
                              void* d_out, int out_size) {
    const float* x   = (const float*)d_in[0];
    const float* ts  = (const float*)d_in[1];
    const float* W1  = (const float*)d_in[2];
    const float* b1  = (const float*)d_in[3];
    const float* W2  = (const float*)d_in[4];
    const float* b2  = (const float*)d_in[5];
    float* out = (float*)d_out;

    cudaFuncSetAttribute(ode_kernel, cudaFuncAttributeMaxDynamicSharedMemorySize,
                         SMEM_BYTES);
    ode_kernel<<<Lc, NT, SMEM_BYTES>>>(x, ts, W1, b1, W2, b2, out);
}

// round 4
// speedup vs baseline: 1.2573x; 1.2573x over previous
#include <cuda_runtime.h>
#include <math.h>

#define Bc   8
#define Lc   96
#define Hc   8
#define Ec   64
#define EHc  128
#define NT   448
#define GRID 152
#define NCH  (Lc * Bc * Hc)   // 6144 independent chains
#define RSLOT 42              // 14 row-groups * 3 rows
#define YP   66               // even pitch -> float2 loads
#define HP   130

// ---- shared memory layout (floats) ----
constexpr int SM_W1  = 0;                        // [64][128]
constexpr int SM_W2  = SM_W1 + Ec * EHc;         // [128][64]
constexpr int SM_B1  = SM_W2 + EHc * Ec;
constexpr int SM_B2  = SM_B1 + EHc;
constexpr int SM_TS  = SM_B2 + Ec;
constexpr int SM_Y   = SM_TS + Lc;               // [42][66]
constexpr int SM_YIN = SM_Y   + RSLOT * YP;
constexpr int SM_K1  = SM_YIN + RSLOT * YP;      // becomes ACC at stage 2
constexpr int SM_K2  = SM_K1  + RSLOT * YP;
constexpr int SM_HS  = SM_K2  + RSLOT * YP;      // [42][130]
constexpr int SM_TOT = SM_HS  + RSLOT * HP;
constexpr int SMEM_BYTES = SM_TOT * 4;           // ~130 KB

typedef unsigned long long ull;

__device__ __forceinline__ ull pk2(float a, float b) {
    ull r; asm("mov.b64 %0, {%1, %2};" : "=l"(r) : "f"(a), "f"(b)); return r;
}
__device__ __forceinline__ void upk2(ull v, float& a, float& b) {
    asm("mov.b64 {%0, %1}, %2;" : "=f"(a), "=f"(b) : "l"(v));
}
__device__ __forceinline__ ull f2fma(ull a, ull b, ull c) {
    ull d; asm("fma.rn.f32x2 %0, %1, %2, %3;" : "=l"(d) : "l"(a), "l"(b), "l"(c));
    return d;
}

// tanh(x) = (e^{2x}-1)/(e^{2x}+1) via MUFU ex2/rcp; |x| clamped to 9
// (tanh(9)=1-5e-8, below fp32 resolution). Abs error ~1e-7.
__device__ __forceinline__ float fast_tanh(float x) {
    float xc = fminf(fmaxf(x, -9.0f), 9.0f);
    float t;
    asm("ex2.approx.f32 %0, %1;" : "=f"(t) : "f"(xc * 2.8853900817779268f));
    float r;
    asm("rcp.approx.f32 %0, %1;" : "=f"(r) : "f"(t + 1.0f));
    return (t - 1.0f) * r;
}

// GEMM1: Hs = tanh(Yin @ W1 + b1). Thread (rg,cg): rows rg*3+i, cols 2cg+{0,1}+64m.
__device__ __forceinline__ void mlp_gemm1(float* sm, const float* __restrict__ Yin,
                                          int rg, int cg) {
    const float* W1 = sm + SM_W1;
    const float* b1 = sm + SM_B1;
    float* Hs = sm + SM_HS;

    ull acc[3][2];
#pragma unroll
    for (int m = 0; m < 2; ++m) {
        float2 bv = *(const float2*)&b1[2 * cg + 64 * m];
        ull bb = pk2(bv.x, bv.y);
#pragma unroll
        for (int i = 0; i < 3; ++i) acc[i][m] = bb;
    }

#pragma unroll 4
    for (int e = 0; e < Ec; e += 2) {
        ull ya[3], yb[3];
#pragma unroll
        for (int i = 0; i < 3; ++i) {
            float2 yv = *(const float2*)&Yin[(rg * 3 + i) * YP + e];
            ya[i] = pk2(yv.x, yv.x);
            yb[i] = pk2(yv.y, yv.y);
        }
#pragma unroll
        for (int m = 0; m < 2; ++m) {
            ull w0 = *(const ull*)&W1[e * EHc + 2 * cg + 64 * m];
            ull w1 = *(const ull*)&W1[(e + 1) * EHc + 2 * cg + 64 * m];
#pragma unroll
            for (int i = 0; i < 3; ++i) {
                acc[i][m] = f2fma(ya[i], w0, acc[i][m]);
                acc[i][m] = f2fma(yb[i], w1, acc[i][m]);
            }
        }
    }

#pragma unroll
    for (int i = 0; i < 3; ++i) {
#pragma unroll
        for (int m = 0; m < 2; ++m) {
            float a, b;
            upk2(acc[i][m], a, b);
            float2 t;
            t.x = fast_tanh(a);
            t.y = fast_tanh(b);
            *(float2*)&Hs[(rg * 3 + i) * HP + 2 * cg + 64 * m] = t;
        }
    }
}

// GEMM2 + stage epilogue. Thread (rg,cg): rows rg*3+i, cols e = 2cg+{0,1}.
// ST=0: K1=k1;  Yin = Y + dt/3*k1
// ST=1: K2=k2;  Yin = Y + dt*k2 - dt/3*K1
// ST=2: K1 <- K1 + 3*(K2 + k3); Yin = Y + dt*(K1 - K2 + k3)
// ST=3: ynew = Y + dt/8*(K1 + k4); emit {x0, ynew}; Y = rst ? x0 : ynew
template <int ST>
__device__ __forceinline__ void mlp_gemm2_epi(float* sm, int rg, int cg,
                                              const float dt[3],
                                              const float2 x0v[3],
                                              const int jo[3],
                                              const bool rst[3],
                                              const bool act[3],
                                              float* __restrict__ out) {
    const float* W2 = sm + SM_W2;
    const float* b2 = sm + SM_B2;
    const float* Hs = sm + SM_HS;
    float* Y   = sm + SM_Y;
    float* Yin = sm + SM_YIN;
    float* K1  = sm + SM_K1;
    float* K2  = sm + SM_K2;

    ull acc[3];
    {
        float2 bv = *(const float2*)&b2[2 * cg];
        ull bb = pk2(bv.x, bv.y);
#pragma unroll
        for (int i = 0; i < 3; ++i) acc[i] = bb;
    }

#pragma unroll 4
    for (int j = 0; j < EHc; j += 2) {
        ull h0[3], h1[3];
#pragma unroll
        for (int i = 0; i < 3; ++i) {
            float2 hv = *(const float2*)&Hs[(rg * 3 + i) * HP + j];
            h0[i] = pk2(hv.x, hv.x);
            h1[i] = pk2(hv.y, hv.y);
        }
        ull w0 = *(const ull*)&W2[j * Ec + 2 * cg];
        ull w1 = *(const ull*)&W2[(j + 1) * Ec + 2 * cg];
#pragma unroll
        for (int i = 0; i < 3; ++i) {
            acc[i] = f2fma(h0[i], w0, acc[i]);
            acc[i] = f2fma(h1[i], w1, acc[i]);
        }
    }

#pragma unroll
    for (int i = 0; i < 3; ++i) {
        int off = (rg * 3 + i) * YP + 2 * cg;
        float o0, o1;
        upk2(acc[i], o0, o1);
        const float d   = dt[i];
        const float d3  = d * (1.0f / 3.0f);
        const float d8  = d * 0.125f;
        if (ST == 0) {
            K1[off] = o0;  K1[off + 1] = o1;
            Yin[off]     = Y[off]     + d3 * o0;
            Yin[off + 1] = Y[off + 1] + d3 * o1;
        } else if (ST == 1) {
            K2[off] = o0;  K2[off + 1] = o1;
            Yin[off]     = Y[off]     + d * o0 - d3 * K1[off];
            Yin[off + 1] = Y[off + 1] + d * o1 - d3 * K1[off + 1];
        } else if (ST == 2) {
            float k1a = K1[off], k1b = K1[off + 1];
            float k2a = K2[off], k2b = K2[off + 1];
            K1[off]     = k1a + 3.0f * (k2a + o0);
            K1[off + 1] = k1b + 3.0f * (k2b + o1);
            Yin[off]     = Y[off]     + d * (k1a - k2a + o0);
            Yin[off + 1] = Y[off + 1] + d * (k1b - k2b + o1);
        } else {
            float yn0 = Y[off]     + d8 * (K1[off] + o0);
            float yn1 = Y[off + 1] + d8 * (K1[off + 1] + o1);
            if (act[i]) {
                float4 v = make_float4(x0v[i].x, yn0, x0v[i].y, yn1);
                *(float4*)&out[jo[i]] = v;
            }
            Y[off]     = rst[i] ? x0v[i].x : yn0;
            Y[off + 1] = rst[i] ? x0v[i].y : yn1;
        }
    }
}

__global__ void __launch_bounds__(NT)
ode_kernel(const float* __restrict__ x, const float* __restrict__ tsg,
           const float* __restrict__ W1g, const float* __restrict__ b1g,
           const float* __restrict__ W2g, const float* __restrict__ b2g,
           float* __restrict__ out) {
    extern __shared__ float sm[];
    const int tid = threadIdx.x;
    const int cg  = tid & 31;   // col group (warp-contiguous)
    const int rg  = tid >> 5;   // row group = warp id

    const int qstart = (blockIdx.x * NCH) / GRID;
    const int qend   = ((blockIdx.x + 1) * NCH) / GRID;
    const int nrows  = qend - qstart;   // 40 or 41

    for (int i = tid; i < Ec * EHc; i += NT) sm[SM_W1 + i] = W1g[i];
    for (int i = tid; i < EHc * Ec; i += NT) sm[SM_W2 + i] = W2g[i];
    if (tid < EHc) sm[SM_B1 + tid] = b1g[tid];
    if (tid < Ec)  sm[SM_B2 + tid] = b2g[tid];
    if (tid < Lc)  sm[SM_TS + tid] = tsg[tid];

    // per-thread chain metadata for 3 owned row slots
    float2 x0v[3];
    int obase[3], idxv[3];
    bool act[3];
#pragma unroll
    for (int i = 0; i < 3; ++i) {
        int r = rg * 3 + i;
        act[i] = (r < nrows);
        int q = qstart + (act[i] ? r : 0);   // inactive slot mirrors chain 0
        int idx = q >> 6;
        int r64 = q & 63;
        int b = r64 >> 3, h = r64 & 7;
        idxv[i] = idx;
        x0v[i] = *(const float2*)&x[((b * Lc + idx) * Hc + h) * Ec + 2 * cg];
        obase[i] = b * (Lc * Lc * Hc * Ec * 2) + idx * (Lc * Hc * Ec * 2) +
                   h * (Ec * 2) + 4 * cg;
        *(float2*)&sm[SM_Y + r * YP + 2 * cg] = x0v[i];
        if (act[i]) {
            // diagonal emission j = idx : state == x0
            float4 v = make_float4(x0v[i].x, x0v[i].x, x0v[i].y, x0v[i].y);
            *(float4*)&out[obase[i] + idx * (Hc * Ec * 2)] = v;
        }
    }
    __syncthreads();

    const float* ts = sm + SM_TS;

    // 95 uniform lockstep RK4 steps per chain:
    // fwd steps k < nf = 95-idx (s = idx+k, emit j = s+1), then reset Y to x0,
    // then bwd steps (s = idx-(k-nf), dt negative, emit j = s-1).
    for (int k = 0; k < Lc - 1; ++k) {
        float dt[3];
        int jo[3];
        bool rst[3];
#pragma unroll
        for (int i = 0; i < 3; ++i) {
            int idx = idxv[i];
            int nf = (Lc - 1) - idx;
            int jj;
            if (k < nf) {
                int s = idx + k;
                dt[i] = ts[s + 1] - ts[s];
                jj = s + 1;
            } else {
                int s = idx - (k - nf);
                dt[i] = ts[s - 1] - ts[s];
                jj = s - 1;
            }
            jo[i]  = obase[i] + jj * (Hc * Ec * 2);
            rst[i] = (k + 1 == nf);
        }

        mlp_gemm1(sm, sm + SM_Y, rg, cg);
        __syncthreads();
        mlp_gemm2_epi<0>(sm, rg, cg, dt, x0v, jo, rst, act, out);
        __syncthreads();
        mlp_gemm1(sm, sm + SM_YIN, rg, cg);
        __syncthreads();
        mlp_gemm2_epi<1>(sm, rg, cg, dt, x0v, jo, rst, act, out);
        __syncthreads();
        mlp_gemm1(sm, sm + SM_YIN, rg, cg);
        __syncthreads();
        mlp_gemm2_epi<2>(sm, rg, cg, dt, x0v, jo, rst, act, out);
        __syncthreads();
        mlp_gemm1(sm, sm + SM_YIN, rg, cg);
        __syncthreads();
        mlp_gemm2_epi<3>(sm, rg, cg, dt, x0v, jo, rst, act, out);
        __syncthreads();
    }
}

extern "C" void kernel_launch(void* const* d_in, const int* in_sizes, int n_in,
                              void* d_out, int out_size) {
    const float* x   = (const float*)d_in[0];
    const float* ts  = (const float*)d_in[1];
    const float* W1  = (const float*)d_in[2];
    const float* b1  = (const float*)d_in[3];
    const float* W2  = (const float*)d_in[4];
    const float* b2  = (const float*)d_in[5];
    float* out = (float*)d_out;

    cudaFuncSetAttribute(ode_kernel, cudaFuncAttributeMaxDynamicSharedMemorySize,
                         SMEM_BYTES);
    ode_kernel<<<GRID, NT, SMEM_BYTES>>>(x, ts, W1, b1, W2, b2, out);
}

// round 6
// speedup vs baseline: 1.3230x; 1.0522x over previous
#include <cuda_runtime.h>
#include <math.h>

#define Bc   8
#define Lc   96
#define Hc   8
#define Ec   64
#define EHc  128
#define NT   224            // 7 warps
#define RPT  6              // rows per thread
#define GRID 152
#define NCH  (Lc * Bc * Hc) // 6144 independent chains
#define RSLOT 42            // 7 warps * 6 rows
#define YP   68             // float4-aligned pitch
#define HP   260            // duplicated hidden row: 256 + pad, float4-aligned

// ---- shared memory layout (floats) ----
constexpr int SM_W1P = 0;                        // [64][128] permuted
constexpr int SM_W2P = SM_W1P + Ec * EHc;        // [64][128] permuted (j-pairs)
constexpr int SM_B1  = SM_W2P + Ec * EHc;        // 16384
constexpr int SM_B2  = SM_B1 + EHc;
constexpr int SM_TS  = SM_B2 + Ec;
constexpr int SM_Y   = SM_TS + Lc;               // [42][68]
constexpr int SM_YIN = SM_Y   + RSLOT * YP;
constexpr int SM_K1  = SM_YIN + RSLOT * YP;
constexpr int SM_K2  = SM_K1  + RSLOT * YP;
constexpr int SM_HD  = SM_K2  + RSLOT * YP;      // [42][260] duplicated (h,h)
constexpr int SM_TOT = SM_HD  + RSLOT * HP;
constexpr int SMEM_BYTES = SM_TOT * 4;           // ~156 KB

typedef unsigned long long ull;

__device__ __forceinline__ ull pk2(float a, float b) {
    ull r; asm("mov.b64 %0, {%1, %2};" : "=l"(r) : "f"(a), "f"(b)); return r;
}
__device__ __forceinline__ void upk2(ull v, float& a, float& b) {
    asm("mov.b64 {%0, %1}, %2;" : "=f"(a), "=f"(b) : "l"(v));
}
__device__ __forceinline__ ull f2fma(ull a, ull b, ull c) {
    ull d; asm("fma.rn.f32x2 %0, %1, %2, %3;" : "=l"(d) : "l"(a), "l"(b), "l"(c));
    return d;
}

// tanh(x) = (e^{2x}-1)/(e^{2x}+1), |x| clamped to 9. Abs err ~1e-7.
__device__ __forceinline__ float fast_tanh(float x) {
    float xc = fminf(fmaxf(x, -9.0f), 9.0f);
    float t;
    asm("ex2.approx.f32 %0, %1;" : "=f"(t) : "f"(xc * 2.8853900817779268f));
    float r;
    asm("rcp.approx.f32 %0, %1;" : "=f"(r) : "f"(t + 1.0f));
    return (t - 1.0f) * r;
}

// GEMM1: Hd = dup(tanh(Yin @ W1 + b1)). Thread (rg,cg): rows rg*6+i,
// cols j in {2cg, 2cg+1, 64+2cg, 64+2cg+1} (via permuted W1p).
__device__ __forceinline__ void mlp_gemm1(float* sm, const float* __restrict__ Yin,
                                          int rg, int cg) {
    const float* W1 = sm + SM_W1P;
    const float* b1 = sm + SM_B1;
    float* Hd = sm + SM_HD;

    ull acc[RPT][2];
    {
        float2 bl = *(const float2*)&b1[2 * cg];
        float2 bh = *(const float2*)&b1[64 + 2 * cg];
        ull b0 = pk2(bl.x, bl.y), b1v = pk2(bh.x, bh.y);
#pragma unroll
        for (int i = 0; i < RPT; ++i) { acc[i][0] = b0; acc[i][1] = b1v; }
    }

#pragma unroll 2
    for (int e = 0; e < Ec; e += 4) {
        float ya[RPT][4];
#pragma unroll
        for (int i = 0; i < RPT; ++i)
            *(float4*)ya[i] = *(const float4*)&Yin[(rg * RPT + i) * YP + e];
#pragma unroll
        for (int ee = 0; ee < 4; ++ee) {
            float4 w = *(const float4*)&W1[(e + ee) * EHc + 4 * cg];
            ull wl = pk2(w.x, w.y), wh = pk2(w.z, w.w);
#pragma unroll
            for (int i = 0; i < RPT; ++i) {
                ull yb = pk2(ya[i][ee], ya[i][ee]);
                acc[i][0] = f2fma(yb, wl, acc[i][0]);
                acc[i][1] = f2fma(yb, wh, acc[i][1]);
            }
        }
    }

#pragma unroll
    for (int i = 0; i < RPT; ++i) {
#pragma unroll
        for (int m = 0; m < 2; ++m) {
            float a, b;
            upk2(acc[i][m], a, b);
            float t0 = fast_tanh(a), t1 = fast_tanh(b);
            int base = (rg * RPT + i) * HP + (m ? 128 + 4 * cg : 4 * cg);
            *(float2*)&Hd[base]     = make_float2(t0, t0);
            *(float2*)&Hd[base + 2] = make_float2(t1, t1);
        }
    }
}

// GEMM2 + stage epilogue. Thread (rg,cg): rows rg*6+i, cols e = 2cg,2cg+1.
// ST=0: K1=k1;  Yin = Y + dt/3*k1
// ST=1: K2=k2;  Yin = Y + dt*k2 - dt/3*K1
// ST=2: K1 <- K1 + 3*(K2 + k3); Yin = Y + dt*(K1 - K2 + k3)
// ST=3: ynew = Y + dt/8*(K1 + k4); emit {x0, ynew}; Y = rst ? x0 : ynew
template <int ST>
__device__ __forceinline__ void mlp_gemm2_epi(float* sm, int rg, int cg,
                                              const float dt[RPT],
                                              const float2 x0v[RPT],
                                              const int jo[RPT],
                                              const bool rst[RPT],
                                              const bool act[RPT],
                                              float* __restrict__ out) {
    const float* W2 = sm + SM_W2P;
    const float* b2 = sm + SM_B2;
    const float* Hd = sm + SM_HD;
    float* Y   = sm + SM_Y;
    float* Yin = sm + SM_YIN;
    float* K1  = sm + SM_K1;
    float* K2  = sm + SM_K2;

    ull acc[RPT];
    {
        float2 bv = *(const float2*)&b2[2 * cg];
        ull bb = pk2(bv.x, bv.y);
#pragma unroll
        for (int i = 0; i < RPT; ++i) acc[i] = bb;
    }

#pragma unroll 4
    for (int jp = 0; jp < EHc / 2; ++jp) {   // j-pair 2jp, 2jp+1
        float4 w = *(const float4*)&W2[jp * 128 + 4 * cg];
        ull wl = pk2(w.x, w.y), wh = pk2(w.z, w.w);
#pragma unroll
        for (int i = 0; i < RPT; ++i) {
            // duplicated storage: float4 = (h0,h0,h1,h1) -> two packed f32x2
            ulonglong2 hv =
                *(const ulonglong2*)&Hd[(rg * RPT + i) * HP + 4 * jp];
            acc[i] = f2fma(hv.x, wl, acc[i]);
            acc[i] = f2fma(hv.y, wh, acc[i]);
        }
    }

#pragma unroll
    for (int i = 0; i < RPT; ++i) {
        int off = (rg * RPT + i) * YP + 2 * cg;
        float o0, o1;
        upk2(acc[i], o0, o1);
        const float d  = dt[i];
        const float d3 = d * (1.0f / 3.0f);
        const float d8 = d * 0.125f;
        float2 yv = *(const float2*)&Y[off];
        if (ST == 0) {
            *(float2*)&K1[off]  = make_float2(o0, o1);
            *(float2*)&Yin[off] = make_float2(yv.x + d3 * o0, yv.y + d3 * o1);
        } else if (ST == 1) {
            float2 k1v = *(const float2*)&K1[off];
            *(float2*)&K2[off]  = make_float2(o0, o1);
            *(float2*)&Yin[off] = make_float2(yv.x + d * o0 - d3 * k1v.x,
                                              yv.y + d * o1 - d3 * k1v.y);
        } else if (ST == 2) {
            float2 k1v = *(const float2*)&K1[off];
            float2 k2v = *(const float2*)&K2[off];
            *(float2*)&K1[off]  = make_float2(k1v.x + 3.0f * (k2v.x + o0),
                                              k1v.y + 3.0f * (k2v.y + o1));
            *(float2*)&Yin[off] = make_float2(yv.x + d * (k1v.x - k2v.x + o0),
                                              yv.y + d * (k1v.y - k2v.y + o1));
        } else {
            float2 k1v = *(const float2*)&K1[off];
            float yn0 = yv.x + d8 * (k1v.x + o0);
            float yn1 = yv.y + d8 * (k1v.y + o1);
            if (act[i]) {
                float4 v = make_float4(x0v[i].x, yn0, x0v[i].y, yn1);
                *(float4*)&out[jo[i]] = v;
            }
            *(float2*)&Y[off] = rst[i] ? x0v[i] : make_float2(yn0, yn1);
        }
    }
}

__global__ void __launch_bounds__(NT)
ode_kernel(const float* __restrict__ x, const float* __restrict__ tsg,
           const float* __restrict__ W1g, const float* __restrict__ b1g,
           const float* __restrict__ W2g, const float* __restrict__ b2g,
           float* __restrict__ out) {
    extern __shared__ float sm[];
    const int tid = threadIdx.x;
    const int cg  = tid & 31;   // column group (lane)
    const int rg  = tid >> 5;   // warp id = row group

    const int qstart = (blockIdx.x * NCH) / GRID;
    const int qend   = ((blockIdx.x + 1) * NCH) / GRID;
    const int nrows  = qend - qstart;   // 40 or 41

    // Permuted W1: W1p[e][c*4+k] <- W1[e][k<2 ? 2c+k : 64+2c+k-2]
    for (int t = tid; t < Ec * EHc; t += NT) {
        int e = t >> 7, p = t & 127, c = p >> 2, k = p & 3;
        int col = (k < 2) ? (2 * c + k) : (64 + 2 * c + (k - 2));
        sm[SM_W1P + t] = W1g[e * EHc + col];
    }
    // Permuted W2: W2p[jp][c*4+k] <- W2[2jp + (k>>1)][2c + (k&1)]
    for (int t = tid; t < (EHc / 2) * 128; t += NT) {
        int jp = t >> 7, p = t & 127, c = p >> 2, k = p & 3;
        sm[SM_W2P + t] = W2g[(2 * jp + (k >> 1)) * Ec + 2 * c + (k & 1)];
    }
    if (tid < EHc) sm[SM_B1 + tid] = b1g[tid];
    if (tid < Ec)  sm[SM_B2 + tid] = b2g[tid];
    if (tid < Lc)  sm[SM_TS + tid] = tsg[tid];

    // per-thread chain metadata for 6 owned row slots
    float2 x0v[RPT];
    int obase[RPT], idxv[RPT];
    bool act[RPT];
#pragma unroll
    for (int i = 0; i < RPT; ++i) {
        int r = rg * RPT + i;
        act[i] = (r < nrows);
        int q = qstart + (act[i] ? r : 0);
        int idx = q >> 6;
        int r64 = q & 63;
        int b = r64 >> 3, h = r64 & 7;
        idxv[i] = idx;
        x0v[i] = *(const float2*)&x[((b * Lc + idx) * Hc + h) * Ec + 2 * cg];
        obase[i] = b * (Lc * Lc * Hc * Ec * 2) + idx * (Lc * Hc * Ec * 2) +
                   h * (Ec * 2) + 4 * cg;
        *(float2*)&sm[SM_Y + r * YP + 2 * cg] = x0v[i];
        if (act[i]) {
            float4 v = make_float4(x0v[i].x, x0v[i].x, x0v[i].y, x0v[i].y);
            *(float4*)&out[obase[i] + idx * (Hc * Ec * 2)] = v;
        }
    }
    __syncthreads();   // weights + ts visible to all warps; after this, warps free-run

    const float* ts = sm + SM_TS;

    // 95 lockstep RK4 steps per chain: fwd k < nf = 95-idx (emit j=s+1),
    // reset to x0, then bwd (dt<0, emit j=s-1). Warp-private rows -> syncwarp only.
    for (int k = 0; k < Lc - 1; ++k) {
        float dt[RPT];
        int jo[RPT];
        bool rst[RPT];
#pragma unroll
        for (int i = 0; i < RPT; ++i) {
            int idx = idxv[i];
            int nf = (Lc - 1) - idx;
            int jj;
            if (k < nf) {
                int s = idx + k;
                dt[i] = ts[s + 1] - ts[s];
                jj = s + 1;
            } else {
                int s = idx - (k - nf);
                dt[i] = ts[s - 1] - ts[s];
                jj = s - 1;
            }
            jo[i]  = obase[i] + jj * (Hc * Ec * 2);
            rst[i] = (k + 1 == nf);
        }

        mlp_gemm1(sm, sm + SM_Y, rg, cg);
        __syncwarp();
        mlp_gemm2_epi<0>(sm, rg, cg, dt, x0v, jo, rst, act, out);
        __syncwarp();
        mlp_gemm1(sm, sm + SM_YIN, rg, cg);
        __syncwarp();
        mlp_gemm2_epi<1>(sm, rg, cg, dt, x0v, jo, rst, act, out);
        __syncwarp();
        mlp_gemm1(sm, sm + SM_YIN, rg, cg);
        __syncwarp();
        mlp_gemm2_epi<2>(sm, rg, cg, dt, x0v, jo, rst, act, out);
        __syncwarp();
        mlp_gemm1(sm, sm + SM_YIN, rg, cg);
        __syncwarp();
        mlp_gemm2_epi<3>(sm, rg, cg, dt, x0v, jo, rst, act, out);
        __syncwarp();
    }
}

extern "C" void kernel_launch(void* const* d_in, const int* in_sizes, int n_in,
                              void* d_out, int out_size) {
    const float* x   = (const float*)d_in[0];
    const float* ts  = (const float*)d_in[1];
    const float* W1  = (const float*)d_in[2];
    const float* b1  = (const float*)d_in[3];
    const float* W2  = (const float*)d_in[4];
    const float* b2  = (const float*)d_in[5];
    float* out = (float*)d_out;

    cudaFuncSetAttribute(ode_kernel, cudaFuncAttributeMaxDynamicSharedMemorySize,
                         SMEM_BYTES);
    ode_kernel<<<GRID, NT, SMEM_BYTES>>>(x, ts, W1, b1, W2, b2, out);
}

// round 7
// speedup vs baseline: 1.3237x; 1.0005x over previous
#include <cuda_runtime.h>
#include <math.h>

#define Bc   8
#define Lc   96
#define Hc   8
#define Ec   64
#define EHc  128
#define NT   224            // 7 warps
#define RPT  6              // rows per thread
#define GRID 152
#define NCH  (Lc * Bc * Hc) // 6144 independent chains
#define RSLOT 42            // 7 warps * 6 rows
#define YP   68             // float4-aligned pitch
#define HP   260            // duplicated hidden row: 256 + pad, float4-aligned

// ---- shared memory layout (floats) ----
constexpr int SM_W1P = 0;                        // [64][128] permuted
constexpr int SM_W2P = SM_W1P + Ec * EHc;        // [64][128] permuted (j-pairs)
constexpr int SM_B1  = SM_W2P + Ec * EHc;        // 16384
constexpr int SM_B2  = SM_B1 + EHc;
constexpr int SM_TS  = SM_B2 + Ec;
constexpr int SM_Y   = SM_TS + Lc;               // [42][68]
constexpr int SM_YIN = SM_Y   + RSLOT * YP;
constexpr int SM_K1  = SM_YIN + RSLOT * YP;
constexpr int SM_K2  = SM_K1  + RSLOT * YP;
constexpr int SM_HD  = SM_K2  + RSLOT * YP;      // [42][260] duplicated (h,h)
constexpr int SM_TOT = SM_HD  + RSLOT * HP;
constexpr int SMEM_BYTES = SM_TOT * 4;           // ~156 KB

typedef unsigned long long ull;

__device__ __forceinline__ ull pk2(float a, float b) {
    ull r; asm("mov.b64 %0, {%1, %2};" : "=l"(r) : "f"(a), "f"(b)); return r;
}
__device__ __forceinline__ void upk2(ull v, float& a, float& b) {
    asm("mov.b64 {%0, %1}, %2;" : "=f"(a), "=f"(b) : "l"(v));
}
__device__ __forceinline__ ull f2fma(ull a, ull b, ull c) {
    ull d; asm("fma.rn.f32x2 %0, %1, %2, %3;" : "=l"(d) : "l"(a), "l"(b), "l"(c));
    return d;
}

// tanh(x) = (e^{2x}-1)/(e^{2x}+1), |x| clamped to 9. Abs err ~1e-7.
__device__ __forceinline__ float fast_tanh(float x) {
    float xc = fminf(fmaxf(x, -9.0f), 9.0f);
    float t;
    asm("ex2.approx.f32 %0, %1;" : "=f"(t) : "f"(xc * 2.8853900817779268f));
    float r;
    asm("rcp.approx.f32 %0, %1;" : "=f"(r) : "f"(t + 1.0f));
    return (t - 1.0f) * r;
}

// GEMM1: Hd = dup(tanh(Yin @ W1 + b1)). Thread (rg,cg): rows rg*6+i,
// cols j in {2cg, 2cg+1, 64+2cg, 64+2cg+1} (via permuted W1p).
__device__ __forceinline__ void mlp_gemm1(float* sm, const float* __restrict__ Yin,
                                          int rg, int cg) {
    const float* W1 = sm + SM_W1P;
    const float* b1 = sm + SM_B1;
    float* Hd = sm + SM_HD;

    ull acc[RPT][2];
    {
        float2 bl = *(const float2*)&b1[2 * cg];
        float2 bh = *(const float2*)&b1[64 + 2 * cg];
        ull b0 = pk2(bl.x, bl.y), b1v = pk2(bh.x, bh.y);
#pragma unroll
        for (int i = 0; i < RPT; ++i) { acc[i][0] = b0; acc[i][1] = b1v; }
    }

#pragma unroll 2
    for (int e = 0; e < Ec; e += 4) {
        float ya[RPT][4];
#pragma unroll
        for (int i = 0; i < RPT; ++i)
            *(float4*)ya[i] = *(const float4*)&Yin[(rg * RPT + i) * YP + e];
#pragma unroll
        for (int ee = 0; ee < 4; ++ee) {
            float4 w = *(const float4*)&W1[(e + ee) * EHc + 4 * cg];
            ull wl = pk2(w.x, w.y), wh = pk2(w.z, w.w);
#pragma unroll
            for (int i = 0; i < RPT; ++i) {
                ull yb = pk2(ya[i][ee], ya[i][ee]);
                acc[i][0] = f2fma(yb, wl, acc[i][0]);
                acc[i][1] = f2fma(yb, wh, acc[i][1]);
            }
        }
    }

#pragma unroll
    for (int i = 0; i < RPT; ++i) {
#pragma unroll
        for (int m = 0; m < 2; ++m) {
            float a, b;
            upk2(acc[i][m], a, b);
            float t0 = fast_tanh(a), t1 = fast_tanh(b);
            int base = (rg * RPT + i) * HP + (m ? 128 + 4 * cg : 4 * cg);
            *(float2*)&Hd[base]     = make_float2(t0, t0);
            *(float2*)&Hd[base + 2] = make_float2(t1, t1);
        }
    }
}

// GEMM2 + stage epilogue. Thread (rg,cg): rows rg*6+i, cols e = 2cg,2cg+1.
// ST=0: K1=k1;  Yin = Y + dt/3*k1
// ST=1: K2=k2;  Yin = Y + dt*k2 - dt/3*K1
// ST=2: K1 <- K1 + 3*(K2 + k3); Yin = Y + dt*(K1 - K2 + k3)
// ST=3: ynew = Y + dt/8*(K1 + k4); emit {x0, ynew}; Y = rst ? x0 : ynew
template <int ST>
__device__ __forceinline__ void mlp_gemm2_epi(float* sm, int rg, int cg,
                                              const float dt[RPT],
                                              const float2 x0v[RPT],
                                              const int jo[RPT],
                                              const bool rst[RPT],
                                              const bool act[RPT],
                                              float* __restrict__ out) {
    const float* W2 = sm + SM_W2P;
    const float* b2 = sm + SM_B2;
    const float* Hd = sm + SM_HD;
    float* Y   = sm + SM_Y;
    float* Yin = sm + SM_YIN;
    float* K1  = sm + SM_K1;
    float* K2  = sm + SM_K2;

    ull acc[RPT];
    {
        float2 bv = *(const float2*)&b2[2 * cg];
        ull bb = pk2(bv.x, bv.y);
#pragma unroll
        for (int i = 0; i < RPT; ++i) acc[i] = bb;
    }

#pragma unroll 4
    for (int jp = 0; jp < EHc / 2; ++jp) {   // j-pair 2jp, 2jp+1
        float4 w = *(const float4*)&W2[jp * 128 + 4 * cg];
        ull wl = pk2(w.x, w.y), wh = pk2(w.z, w.w);
#pragma unroll
        for (int i = 0; i < RPT; ++i) {
            // duplicated storage: float4 = (h0,h0,h1,h1) -> two packed f32x2
            ulonglong2 hv =
                *(const ulonglong2*)&Hd[(rg * RPT + i) * HP + 4 * jp];
            acc[i] = f2fma(hv.x, wl, acc[i]);
            acc[i] = f2fma(hv.y, wh, acc[i]);
        }
    }

#pragma unroll
    for (int i = 0; i < RPT; ++i) {
        int off = (rg * RPT + i) * YP + 2 * cg;
        float o0, o1;
        upk2(acc[i], o0, o1);
        const float d  = dt[i];
        const float d3 = d * (1.0f / 3.0f);
        const float d8 = d * 0.125f;
        float2 yv = *(const float2*)&Y[off];
        if (ST == 0) {
            *(float2*)&K1[off]  = make_float2(o0, o1);
            *(float2*)&Yin[off] = make_float2(yv.x + d3 * o0, yv.y + d3 * o1);
        } else if (ST == 1) {
            float2 k1v = *(const float2*)&K1[off];
            *(float2*)&K2[off]  = make_float2(o0, o1);
            *(float2*)&Yin[off] = make_float2(yv.x + d * o0 - d3 * k1v.x,
                                              yv.y + d * o1 - d3 * k1v.y);
        } else if (ST == 2) {
            float2 k1v = *(const float2*)&K1[off];
            float2 k2v = *(const float2*)&K2[off];
            *(float2*)&K1[off]  = make_float2(k1v.x + 3.0f * (k2v.x + o0),
                                              k1v.y + 3.0f * (k2v.y + o1));
            *(float2*)&Yin[off] = make_float2(yv.x + d * (k1v.x - k2v.x + o0),
                                              yv.y + d * (k1v.y - k2v.y + o1));
        } else {
            float2 k1v = *(const float2*)&K1[off];
            float yn0 = yv.x + d8 * (k1v.x + o0);
            float yn1 = yv.y + d8 * (k1v.y + o1);
            if (act[i]) {
                float4 v = make_float4(x0v[i].x, yn0, x0v[i].y, yn1);
                *(float4*)&out[jo[i]] = v;
            }
            *(float2*)&Y[off] = rst[i] ? x0v[i] : make_float2(yn0, yn1);
        }
    }
}

__global__ void __launch_bounds__(NT)
ode_kernel(const float* __restrict__ x, const float* __restrict__ tsg,
           const float* __restrict__ W1g, const float* __restrict__ b1g,
           const float* __restrict__ W2g, const float* __restrict__ b2g,
           float* __restrict__ out) {
    extern __shared__ float sm[];
    const int tid = threadIdx.x;
    const int cg  = tid & 31;   // column group (lane)
    const int rg  = tid >> 5;   // warp id = row group

    const int qstart = (blockIdx.x * NCH) / GRID;
    const int qend   = ((blockIdx.x + 1) * NCH) / GRID;
    const int nrows  = qend - qstart;   // 40 or 41

    // Permuted W1: W1p[e][c*4+k] <- W1[e][k<2 ? 2c+k : 64+2c+k-2]
    for (int t = tid; t < Ec * EHc; t += NT) {
        int e = t >> 7, p = t & 127, c = p >> 2, k = p & 3;
        int col = (k < 2) ? (2 * c + k) : (64 + 2 * c + (k - 2));
        sm[SM_W1P + t] = W1g[e * EHc + col];
    }
    // Permuted W2: W2p[jp][c*4+k] <- W2[2jp + (k>>1)][2c + (k&1)]
    for (int t = tid; t < (EHc / 2) * 128; t += NT) {
        int jp = t >> 7, p = t & 127, c = p >> 2, k = p & 3;
        sm[SM_W2P + t] = W2g[(2 * jp + (k >> 1)) * Ec + 2 * c + (k & 1)];
    }
    if (tid < EHc) sm[SM_B1 + tid] = b1g[tid];
    if (tid < Ec)  sm[SM_B2 + tid] = b2g[tid];
    if (tid < Lc)  sm[SM_TS + tid] = tsg[tid];

    // per-thread chain metadata for 6 owned row slots
    float2 x0v[RPT];
    int obase[RPT], idxv[RPT];
    bool act[RPT];
#pragma unroll
    for (int i = 0; i < RPT; ++i) {
        int r = rg * RPT + i;
        act[i] = (r < nrows);
        int q = qstart + (act[i] ? r : 0);
        int idx = q >> 6;
        int r64 = q & 63;
        int b = r64 >> 3, h = r64 & 7;
        idxv[i] = idx;
        x0v[i] = *(const float2*)&x[((b * Lc + idx) * Hc + h) * Ec + 2 * cg];
        obase[i] = b * (Lc * Lc * Hc * Ec * 2) + idx * (Lc * Hc * Ec * 2) +
                   h * (Ec * 2) + 4 * cg;
        *(float2*)&sm[SM_Y + r * YP + 2 * cg] = x0v[i];
        if (act[i]) {
            float4 v = make_float4(x0v[i].x, x0v[i].x, x0v[i].y, x0v[i].y);
            *(float4*)&out[obase[i] + idx * (Hc * Ec * 2)] = v;
        }
    }
    __syncthreads();   // weights + ts visible to all warps; after this, warps free-run

    const float* ts = sm + SM_TS;

    // 95 lockstep RK4 steps per chain: fwd k < nf = 95-idx (emit j=s+1),
    // reset to x0, then bwd (dt<0, emit j=s-1). Warp-private rows -> syncwarp only.
    for (int k = 0; k < Lc - 1; ++k) {
        float dt[RPT];
        int jo[RPT];
        bool rst[RPT];
#pragma unroll
        for (int i = 0; i < RPT; ++i) {
            int idx = idxv[i];
            int nf = (Lc - 1) - idx;
            int jj;
            if (k < nf) {
                int s = idx + k;
                dt[i] = ts[s + 1] - ts[s];
                jj = s + 1;
            } else {
                int s = idx - (k - nf);
                dt[i] = ts[s - 1] - ts[s];
                jj = s - 1;
            }
            jo[i]  = obase[i] + jj * (Hc * Ec * 2);
            rst[i] = (k + 1 == nf);
        }

        mlp_gemm1(sm, sm + SM_Y, rg, cg);
        __syncwarp();
        mlp_gemm2_epi<0>(sm, rg, cg, dt, x0v, jo, rst, act, out);
        __syncwarp();
        mlp_gemm1(sm, sm + SM_YIN, rg, cg);
        __syncwarp();
        mlp_gemm2_epi<1>(sm, rg, cg, dt, x0v, jo, rst, act, out);
        __syncwarp();
        mlp_gemm1(sm, sm + SM_YIN, rg, cg);
        __syncwarp();
        mlp_gemm2_epi<2>(sm, rg, cg, dt, x0v, jo, rst, act, out);
        __syncwarp();
        mlp_gemm1(sm, sm + SM_YIN, rg, cg);
        __syncwarp();
        mlp_gemm2_epi<3>(sm, rg, cg, dt, x0v, jo, rst, act, out);
        __syncwarp();
    }
}

extern "C" void kernel_launch(void* const* d_in, const int* in_sizes, int n_in,
                              void* d_out, int out_size) {
    const float* x   = (const float*)d_in[0];
    const float* ts  = (const float*)d_in[1];
    const float* W1  = (const float*)d_in[2];
    const float* b1  = (const float*)d_in[3];
    const float* W2  = (const float*)d_in[4];
    const float* b2  = (const float*)d_in[5];
    float* out = (float*)d_out;

    cudaFuncSetAttribute(ode_kernel, cudaFuncAttributeMaxDynamicSharedMemorySize,
                         SMEM_BYTES);
    ode_kernel<<<GRID, NT, SMEM_BYTES>>>(x, ts, W1, b1, W2, b2, out);
}

// round 8
// speedup vs baseline: 1.3240x; 1.0002x over previous
#include <cuda_runtime.h>
#include <math.h>

#define Bc   8
#define Lc   96
#define Hc   8
#define Ec   64
#define EHc  128
#define NT   224            // 7 warps
#define RPT  6              // rows per thread
#define GRID 152
#define NCH  (Lc * Bc * Hc) // 6144 independent chains
#define RSLOT 42            // 7 warps * 6 rows
#define YP   68             // float4-aligned pitch
#define HP   260            // duplicated hidden row: 256 + pad, float4-aligned

// ---- shared memory layout (floats) ----
constexpr int SM_W1P = 0;                        // [64][128] permuted
constexpr int SM_W2P = SM_W1P + Ec * EHc;        // [64][128] permuted (j-pairs)
constexpr int SM_B1  = SM_W2P + Ec * EHc;        // 16384
constexpr int SM_B2  = SM_B1 + EHc;
constexpr int SM_TS  = SM_B2 + Ec;
constexpr int SM_Y   = SM_TS + Lc;               // [42][68]
constexpr int SM_YIN = SM_Y   + RSLOT * YP;
constexpr int SM_K1  = SM_YIN + RSLOT * YP;
constexpr int SM_K2  = SM_K1  + RSLOT * YP;
constexpr int SM_HD  = SM_K2  + RSLOT * YP;      // [42][260] duplicated (h,h)
constexpr int SM_TOT = SM_HD  + RSLOT * HP;
constexpr int SMEM_BYTES = SM_TOT * 4;           // ~156 KB

typedef unsigned long long ull;

__device__ __forceinline__ ull pk2(float a, float b) {
    ull r; asm("mov.b64 %0, {%1, %2};" : "=l"(r) : "f"(a), "f"(b)); return r;
}
__device__ __forceinline__ void upk2(ull v, float& a, float& b) {
    asm("mov.b64 {%0, %1}, %2;" : "=f"(a), "=f"(b) : "l"(v));
}
__device__ __forceinline__ ull f2fma(ull a, ull b, ull c) {
    ull d; asm("fma.rn.f32x2 %0, %1, %2, %3;" : "=l"(d) : "l"(a), "l"(b), "l"(c));
    return d;
}

// tanh(x) = (e^{2x}-1)/(e^{2x}+1), |x| clamped to 9. Abs err ~1e-7.
__device__ __forceinline__ float fast_tanh(float x) {
    float xc = fminf(fmaxf(x, -9.0f), 9.0f);
    float t;
    asm("ex2.approx.f32 %0, %1;" : "=f"(t) : "f"(xc * 2.8853900817779268f));
    float r;
    asm("rcp.approx.f32 %0, %1;" : "=f"(r) : "f"(t + 1.0f));
    return (t - 1.0f) * r;
}

// GEMM1: Hd = dup(tanh(Yin @ W1 + b1)). Thread (rg,cg): rows rg*6+i,
// cols j in {2cg, 2cg+1, 64+2cg, 64+2cg+1} (via permuted W1p).
__device__ __forceinline__ void mlp_gemm1(float* sm, const float* __restrict__ Yin,
                                          int rg, int cg) {
    const float* W1 = sm + SM_W1P;
    const float* b1 = sm + SM_B1;
    float* Hd = sm + SM_HD;

    ull acc[RPT][2];
    {
        float2 bl = *(const float2*)&b1[2 * cg];
        float2 bh = *(const float2*)&b1[64 + 2 * cg];
        ull b0 = pk2(bl.x, bl.y), b1v = pk2(bh.x, bh.y);
#pragma unroll
        for (int i = 0; i < RPT; ++i) { acc[i][0] = b0; acc[i][1] = b1v; }
    }

#pragma unroll 2
    for (int e = 0; e < Ec; e += 4) {
        float ya[RPT][4];
#pragma unroll
        for (int i = 0; i < RPT; ++i)
            *(float4*)ya[i] = *(const float4*)&Yin[(rg * RPT + i) * YP + e];
#pragma unroll
        for (int ee = 0; ee < 4; ++ee) {
            float4 w = *(const float4*)&W1[(e + ee) * EHc + 4 * cg];
            ull wl = pk2(w.x, w.y), wh = pk2(w.z, w.w);
#pragma unroll
            for (int i = 0; i < RPT; ++i) {
                ull yb = pk2(ya[i][ee], ya[i][ee]);
                acc[i][0] = f2fma(yb, wl, acc[i][0]);
                acc[i][1] = f2fma(yb, wh, acc[i][1]);
            }
        }
    }

#pragma unroll
    for (int i = 0; i < RPT; ++i) {
#pragma unroll
        for (int m = 0; m < 2; ++m) {
            float a, b;
            upk2(acc[i][m], a, b);
            float t0 = fast_tanh(a), t1 = fast_tanh(b);
            int base = (rg * RPT + i) * HP + (m ? 128 + 4 * cg : 4 * cg);
            *(float2*)&Hd[base]     = make_float2(t0, t0);
            *(float2*)&Hd[base + 2] = make_float2(t1, t1);
        }
    }
}

// GEMM2 + stage epilogue. Thread (rg,cg): rows rg*6+i, cols e = 2cg,2cg+1.
// ST=0: K1=k1;  Yin = Y + dt/3*k1
// ST=1: K2=k2;  Yin = Y + dt*k2 - dt/3*K1
// ST=2: K1 <- K1 + 3*(K2 + k3); Yin = Y + dt*(K1 - K2 + k3)
// ST=3: ynew = Y + dt/8*(K1 + k4); emit {x0, ynew}; Y = rst ? x0 : ynew
template <int ST>
__device__ __forceinline__ void mlp_gemm2_epi(float* sm, int rg, int cg,
                                              const float dt[RPT],
                                              const float2 x0v[RPT],
                                              const int jo[RPT],
                                              const bool rst[RPT],
                                              const bool act[RPT],
                                              float* __restrict__ out) {
    const float* W2 = sm + SM_W2P;
    const float* b2 = sm + SM_B2;
    const float* Hd = sm + SM_HD;
    float* Y   = sm + SM_Y;
    float* Yin = sm + SM_YIN;
    float* K1  = sm + SM_K1;
    float* K2  = sm + SM_K2;

    ull acc[RPT];
    {
        float2 bv = *(const float2*)&b2[2 * cg];
        ull bb = pk2(bv.x, bv.y);
#pragma unroll
        for (int i = 0; i < RPT; ++i) acc[i] = bb;
    }

#pragma unroll 4
    for (int jp = 0; jp < EHc / 2; ++jp) {   // j-pair 2jp, 2jp+1
        float4 w = *(const float4*)&W2[jp * 128 + 4 * cg];
        ull wl = pk2(w.x, w.y), wh = pk2(w.z, w.w);
#pragma unroll
        for (int i = 0; i < RPT; ++i) {
            // duplicated storage: float4 = (h0,h0,h1,h1) -> two packed f32x2
            ulonglong2 hv =
                *(const ulonglong2*)&Hd[(rg * RPT + i) * HP + 4 * jp];
            acc[i] = f2fma(hv.x, wl, acc[i]);
            acc[i] = f2fma(hv.y, wh, acc[i]);
        }
    }

#pragma unroll
    for (int i = 0; i < RPT; ++i) {
        int off = (rg * RPT + i) * YP + 2 * cg;
        float o0, o1;
        upk2(acc[i], o0, o1);
        const float d  = dt[i];
        const float d3 = d * (1.0f / 3.0f);
        const float d8 = d * 0.125f;
        float2 yv = *(const float2*)&Y[off];
        if (ST == 0) {
            *(float2*)&K1[off]  = make_float2(o0, o1);
            *(float2*)&Yin[off] = make_float2(yv.x + d3 * o0, yv.y + d3 * o1);
        } else if (ST == 1) {
            float2 k1v = *(const float2*)&K1[off];
            *(float2*)&K2[off]  = make_float2(o0, o1);
            *(float2*)&Yin[off] = make_float2(yv.x + d * o0 - d3 * k1v.x,
                                              yv.y + d * o1 - d3 * k1v.y);
        } else if (ST == 2) {
            float2 k1v = *(const float2*)&K1[off];
            float2 k2v = *(const float2*)&K2[off];
            *(float2*)&K1[off]  = make_float2(k1v.x + 3.0f * (k2v.x + o0),
                                              k1v.y + 3.0f * (k2v.y + o1));
            *(float2*)&Yin[off] = make_float2(yv.x + d * (k1v.x - k2v.x + o0),
                                              yv.y + d * (k1v.y - k2v.y + o1));
        } else {
            float2 k1v = *(const float2*)&K1[off];
            float yn0 = yv.x + d8 * (k1v.x + o0);
            float yn1 = yv.y + d8 * (k1v.y + o1);
            if (act[i]) {
                float4 v = make_float4(x0v[i].x, yn0, x0v[i].y, yn1);
                *(float4*)&out[jo[i]] = v;
            }
            *(float2*)&Y[off] = rst[i] ? x0v[i] : make_float2(yn0, yn1);
        }
    }
}

__global__ void __launch_bounds__(NT)
ode_kernel(const float* __restrict__ x, const float* __restrict__ tsg,
           const float* __restrict__ W1g, const float* __restrict__ b1g,
           const float* __restrict__ W2g, const float* __restrict__ b2g,
           float* __restrict__ out) {
    extern __shared__ float sm[];
    const int tid = threadIdx.x;
    const int cg  = tid & 31;   // column group (lane)
    const int rg  = tid >> 5;   // warp id = row group

    const int qstart = (blockIdx.x * NCH) / GRID;
    const int qend   = ((blockIdx.x + 1) * NCH) / GRID;
    const int nrows  = qend - qstart;   // 40 or 41

    // Permuted W1: W1p[e][c*4+k] <- W1[e][k<2 ? 2c+k : 64+2c+k-2]
    for (int t = tid; t < Ec * EHc; t += NT) {
        int e = t >> 7, p = t & 127, c = p >> 2, k = p & 3;
        int col = (k < 2) ? (2 * c + k) : (64 + 2 * c + (k - 2));
        sm[SM_W1P + t] = W1g[e * EHc + col];
    }
    // Permuted W2: W2p[jp][c*4+k] <- W2[2jp + (k>>1)][2c + (k&1)]
    for (int t = tid; t < (EHc / 2) * 128; t += NT) {
        int jp = t >> 7, p = t & 127, c = p >> 2, k = p & 3;
        sm[SM_W2P + t] = W2g[(2 * jp + (k >> 1)) * Ec + 2 * c + (k & 1)];
    }
    if (tid < EHc) sm[SM_B1 + tid] = b1g[tid];
    if (tid < Ec)  sm[SM_B2 + tid] = b2g[tid];
    if (tid < Lc)  sm[SM_TS + tid] = tsg[tid];

    // per-thread chain metadata for 6 owned row slots
    float2 x0v[RPT];
    int obase[RPT], idxv[RPT];
    bool act[RPT];
#pragma unroll
    for (int i = 0; i < RPT; ++i) {
        int r = rg * RPT + i;
        act[i] = (r < nrows);
        int q = qstart + (act[i] ? r : 0);
        int idx = q >> 6;
        int r64 = q & 63;
        int b = r64 >> 3, h = r64 & 7;
        idxv[i] = idx;
        x0v[i] = *(const float2*)&x[((b * Lc + idx) * Hc + h) * Ec + 2 * cg];
        obase[i] = b * (Lc * Lc * Hc * Ec * 2) + idx * (Lc * Hc * Ec * 2) +
                   h * (Ec * 2) + 4 * cg;
        *(float2*)&sm[SM_Y + r * YP + 2 * cg] = x0v[i];
        if (act[i]) {
            float4 v = make_float4(x0v[i].x, x0v[i].x, x0v[i].y, x0v[i].y);
            *(float4*)&out[obase[i] + idx * (Hc * Ec * 2)] = v;
        }
    }
    __syncthreads();   // weights + ts visible to all warps; after this, warps free-run

    const float* ts = sm + SM_TS;

    // 95 lockstep RK4 steps per chain: fwd k < nf = 95-idx (emit j=s+1),
    // reset to x0, then bwd (dt<0, emit j=s-1). Warp-private rows -> syncwarp only.
    for (int k = 0; k < Lc - 1; ++k) {
        float dt[RPT];
        int jo[RPT];
        bool rst[RPT];
#pragma unroll
        for (int i = 0; i < RPT; ++i) {
            int idx = idxv[i];
            int nf = (Lc - 1) - idx;
            int jj;
            if (k < nf) {
                int s = idx + k;
                dt[i] = ts[s + 1] - ts[s];
                jj = s + 1;
            } else {
                int s = idx - (k - nf);
                dt[i] = ts[s - 1] - ts[s];
                jj = s - 1;
            }
            jo[i]  = obase[i] + jj * (Hc * Ec * 2);
            rst[i] = (k + 1 == nf);
        }

        mlp_gemm1(sm, sm + SM_Y, rg, cg);
        __syncwarp();
        mlp_gemm2_epi<0>(sm, rg, cg, dt, x0v, jo, rst, act, out);
        __syncwarp();
        mlp_gemm1(sm, sm + SM_YIN, rg, cg);
        __syncwarp();
        mlp_gemm2_epi<1>(sm, rg, cg, dt, x0v, jo, rst, act, out);
        __syncwarp();
        mlp_gemm1(sm, sm + SM_YIN, rg, cg);
        __syncwarp();
        mlp_gemm2_epi<2>(sm, rg, cg, dt, x0v, jo, rst, act, out);
        __syncwarp();
        mlp_gemm1(sm, sm + SM_YIN, rg, cg);
        __syncwarp();
        mlp_gemm2_epi<3>(sm, rg, cg, dt, x0v, jo, rst, act, out);
        __syncwarp();
    }
}

extern "C" void kernel_launch(void* const* d_in, const int* in_sizes, int n_in,
                              void* d_out, int out_size) {
    const float* x   = (const float*)d_in[0];
    const float* ts  = (const float*)d_in[1];
    const float* W1  = (const float*)d_in[2];
    const float* b1  = (const float*)d_in[3];
    const float* W2  = (const float*)d_in[4];
    const float* b2  = (const float*)d_in[5];
    float* out = (float*)d_out;

    cudaFuncSetAttribute(ode_kernel, cudaFuncAttributeMaxDynamicSharedMemorySize,
                         SMEM_BYTES);
    ode_kernel<<<GRID, NT, SMEM_BYTES>>>(x, ts, W1, b1, W2, b2, out);
}

// round 9
// speedup vs baseline: 1.4306x; 1.0805x over previous
#include <cuda_runtime.h>

#define Bc_  8
#define Lc   96
#define Hc   8
#define Ec   64
#define EHc  128
#define NT   128
#define GRID 152
#define NCH  (Lc * Bc_ * Hc)
#define NPS  6          // row-pairs per warp
#define YP   132        // floats per pair-row (128 data + pad)
#define HPP  260        // floats per hidden pair-row (256 data + pad)

constexpr int SM_W1  = 0;                     // [64][128]
constexpr int SM_W2P = SM_W1 + Ec * EHc;      // [64][128] permuted
constexpr int SM_B1  = SM_W2P + Ec * EHc;
constexpr int SM_B2  = SM_B1 + EHc;
constexpr int SM_TS  = SM_B2 + Ec;
constexpr int SM_Y   = SM_TS + Lc;            // [24][132]
constexpr int SM_YIN = SM_Y   + 24 * YP;
constexpr int SM_K1  = SM_YIN + 24 * YP;
constexpr int SM_K2  = SM_K1  + 24 * YP;
constexpr int SM_HP  = SM_K2  + 24 * YP;      // [24][260]
constexpr int SM_TOT = SM_HP  + 24 * HPP;
constexpr int SMEM_BYTES = SM_TOT * 4;        // ~139 KB

typedef unsigned long long ull;

__device__ __forceinline__ ull pk2(float a, float b) {
    ull r; asm("mov.b64 %0, {%1, %2};" : "=l"(r) : "f"(a), "f"(b)); return r;
}
__device__ __forceinline__ void upk2(ull v, float& a, float& b) {
    asm("mov.b64 {%0, %1}, %2;" : "=f"(a), "=f"(b) : "l"(v));
}
__device__ __forceinline__ ull f2fma(ull a, ull b, ull c) {
    ull d; asm("fma.rn.f32x2 %0, %1, %2, %3;" : "=l"(d) : "l"(a), "l"(b), "l"(c));
    return d;
}
__device__ __forceinline__ ull add2(ull a, ull b) {
    ull d; asm("add.rn.f32x2 %0, %1, %2;" : "=l"(d) : "l"(a), "l"(b)); return d;
}
__device__ __forceinline__ ull mul2(ull a, ull b) {
    ull d; asm("mul.rn.f32x2 %0, %1, %2;" : "=l"(d) : "l"(a), "l"(b)); return d;
}

// tanh(x) = (e^{2x}-1)/(e^{2x}+1), clamp |x|<=9. Abs err ~1e-7.
__device__ __forceinline__ float fast_tanh(float x) {
    float xc = fminf(fmaxf(x, -9.0f), 9.0f);
    float t;
    asm("ex2.approx.f32 %0, %1;" : "=f"(t) : "f"(xc * 2.8853900817779268f));
    float r;
    asm("rcp.approx.f32 %0, %1;" : "=f"(r) : "f"(t + 1.0f));
    return (t - 1.0f) * r;
}

// GEMM1: Hp = tanh(Yin@W1 + b1), pair-packed rows. Lane cg: cols 4cg..4cg+3.
// Hidden pair for col j stored at pair-row offset 64*(j&3) + 2*(j>>2).
__device__ __forceinline__ void gemm1(float* sm, int ybase, int cg, int pb) {
    const float* __restrict__ W1 = sm + SM_W1;
    float4 bv = *(const float4*)&sm[SM_B1 + 4 * cg];
    ull acc[NPS][4];
    {
        ull b0 = pk2(bv.x, bv.x), b1 = pk2(bv.y, bv.y);
        ull b2 = pk2(bv.z, bv.z), b3 = pk2(bv.w, bv.w);
#pragma unroll
        for (int p = 0; p < NPS; ++p) {
            acc[p][0] = b0; acc[p][1] = b1; acc[p][2] = b2; acc[p][3] = b3;
        }
    }
#pragma unroll 4
    for (int ep = 0; ep < 32; ++ep) {
        float4 wa = *(const float4*)&W1[(2 * ep) * EHc + 4 * cg];
        float4 wb = *(const float4*)&W1[(2 * ep + 1) * EHc + 4 * cg];
        ull wa0 = pk2(wa.x, wa.x), wa1 = pk2(wa.y, wa.y);
        ull wa2 = pk2(wa.z, wa.z), wa3 = pk2(wa.w, wa.w);
        ull wb0 = pk2(wb.x, wb.x), wb1 = pk2(wb.y, wb.y);
        ull wb2 = pk2(wb.z, wb.z), wb3 = pk2(wb.w, wb.w);
#pragma unroll
        for (int p = 0; p < NPS; ++p) {
            ulonglong2 yv = *(const ulonglong2*)&sm[ybase + (pb + p) * YP + 4 * ep];
            acc[p][0] = f2fma(yv.x, wa0, acc[p][0]);
            acc[p][1] = f2fma(yv.x, wa1, acc[p][1]);
            acc[p][2] = f2fma(yv.x, wa2, acc[p][2]);
            acc[p][3] = f2fma(yv.x, wa3, acc[p][3]);
            acc[p][0] = f2fma(yv.y, wb0, acc[p][0]);
            acc[p][1] = f2fma(yv.y, wb1, acc[p][1]);
            acc[p][2] = f2fma(yv.y, wb2, acc[p][2]);
            acc[p][3] = f2fma(yv.y, wb3, acc[p][3]);
        }
    }
#pragma unroll
    for (int p = 0; p < NPS; ++p) {
        float* hr = sm + SM_HP + (pb + p) * HPP;
#pragma unroll
        for (int c = 0; c < 4; ++c) {
            float a, b;
            upk2(acc[p][c], a, b);
            *(float2*)&hr[64 * c + 2 * cg] = make_float2(fast_tanh(a), fast_tanh(b));
        }
    }
}

// GEMM2 + RK4 stage. Lane cg: out cols e = 2cg, 2cg+1 (pair-packed rows).
template <int ST>
__device__ __forceinline__ void gemm2_epi(float* sm, int cg, int pb,
                                          const ull dp[NPS], const float4 x0p[NPS],
                                          const int joA[NPS], const int joB[NPS],
                                          unsigned rstAm, unsigned rstBm,
                                          unsigned actAm, unsigned actBm,
                                          float* __restrict__ out) {
    const float* __restrict__ W2 = sm + SM_W2P;
    float2 b2v = *(const float2*)&sm[SM_B2 + 2 * cg];
    ull acc[NPS][2];
    {
        ull c0 = pk2(b2v.x, b2v.x), c1 = pk2(b2v.y, b2v.y);
#pragma unroll
        for (int p = 0; p < NPS; ++p) { acc[p][0] = c0; acc[p][1] = c1; }
    }
#pragma unroll 4
    for (int u = 0; u < 64; ++u) {
        float4 w = *(const float4*)&W2[u * EHc + 4 * cg];
        ull w00 = pk2(w.x, w.x), w01 = pk2(w.y, w.y);
        ull w10 = pk2(w.z, w.z), w11 = pk2(w.w, w.w);
#pragma unroll
        for (int p = 0; p < NPS; ++p) {
            ulonglong2 hv = *(const ulonglong2*)&sm[SM_HP + (pb + p) * HPP + 4 * u];
            acc[p][0] = f2fma(hv.x, w00, acc[p][0]);
            acc[p][1] = f2fma(hv.x, w01, acc[p][1]);
            acc[p][0] = f2fma(hv.y, w10, acc[p][0]);
            acc[p][1] = f2fma(hv.y, w11, acc[p][1]);
        }
    }

    const ull THIRDC  = pk2(1.0f / 3.0f, 1.0f / 3.0f);
    const ull NTHIRDC = pk2(-1.0f / 3.0f, -1.0f / 3.0f);
    const ull EIGHTHC = pk2(0.125f, 0.125f);
    const ull THREEC  = pk2(3.0f, 3.0f);
    const ull NEGONEC = pk2(-1.0f, -1.0f);

#pragma unroll
    for (int p = 0; p < NPS; ++p) {
        float* yr  = sm + SM_Y   + (pb + p) * YP + 4 * cg;
        float* yi  = sm + SM_YIN + (pb + p) * YP + 4 * cg;
        float* k1r = sm + SM_K1  + (pb + p) * YP + 4 * cg;
        float* k2r = sm + SM_K2  + (pb + p) * YP + 4 * cg;
        ulonglong2 yv = *(const ulonglong2*)yr;
        ull o0 = acc[p][0], o1 = acc[p][1];
        ull d = dp[p];
        if (ST == 0) {
            *(ulonglong2*)k1r = make_ulonglong2(o0, o1);
            ull d3 = mul2(d, THIRDC);
            *(ulonglong2*)yi = make_ulonglong2(f2fma(o0, d3, yv.x),
                                               f2fma(o1, d3, yv.y));
        } else if (ST == 1) {
            ulonglong2 k1 = *(const ulonglong2*)k1r;
            *(ulonglong2*)k2r = make_ulonglong2(o0, o1);
            ull nd3 = mul2(d, NTHIRDC);
            ull t0 = f2fma(k1.x, nd3, yv.x);
            ull t1 = f2fma(k1.y, nd3, yv.y);
            *(ulonglong2*)yi = make_ulonglong2(f2fma(o0, d, t0), f2fma(o1, d, t1));
        } else if (ST == 2) {
            ulonglong2 k1 = *(const ulonglong2*)k1r;
            ulonglong2 k2 = *(const ulonglong2*)k2r;
            ull s0 = add2(k2.x, o0), s1 = add2(k2.y, o1);
            *(ulonglong2*)k1r = make_ulonglong2(f2fma(s0, THREEC, k1.x),
                                                f2fma(s1, THREEC, k1.y));
            ull a0 = add2(k1.x, o0), a1 = add2(k1.y, o1);
            ull u0 = f2fma(k2.x, NEGONEC, a0);
            ull u1 = f2fma(k2.y, NEGONEC, a1);
            *(ulonglong2*)yi = make_ulonglong2(f2fma(u0, d, yv.x),
                                               f2fma(u1, d, yv.y));
        } else {
            ulonglong2 k1 = *(const ulonglong2*)k1r;
            ull d8 = mul2(d, EIGHTHC);
            ull yn0 = f2fma(add2(k1.x, o0), d8, yv.x);
            ull yn1 = f2fma(add2(k1.y, o1), d8, yv.y);
            float yA0, yB0, yA1, yB1;
            upk2(yn0, yA0, yB0);
            upk2(yn1, yA1, yB1);
            if ((actAm >> p) & 1)
                *(float4*)&out[joA[p]] = make_float4(x0p[p].x, yA0, x0p[p].y, yA1);
            if ((actBm >> p) & 1)
                *(float4*)&out[joB[p]] = make_float4(x0p[p].z, yB0, x0p[p].w, yB1);
            bool rA = (rstAm >> p) & 1, rB = (rstBm >> p) & 1;
            *(float4*)yr = make_float4(rA ? x0p[p].x : yA0, rB ? x0p[p].z : yB0,
                                       rA ? x0p[p].y : yA1, rB ? x0p[p].w : yB1);
        }
    }
}

__global__ void __launch_bounds__(NT, 1)
ode_kernel(const float* __restrict__ x, const float* __restrict__ tsg,
           const float* __restrict__ W1g, const float* __restrict__ b1g,
           const float* __restrict__ W2g, const float* __restrict__ b2g,
           float* __restrict__ out) {
    extern __shared__ float sm[];
    const int tid = threadIdx.x;
    const int cg  = tid & 31;
    const int wid = tid >> 5;
    const int pb  = wid * NPS;

    const int qstart = (blockIdx.x * NCH) / GRID;
    const int qend   = ((blockIdx.x + 1) * NCH) / GRID;
    const int nrows  = qend - qstart;          // 40 or 41
    const int rowbase = wid * 2 * NPS;         // 12 rows per warp
    int awc = nrows - rowbase;
    const int aw = awc < 0 ? 0 : awc;          // active rows in this warp

    // W1 row-major copy
    for (int t = tid; t < Ec * EHc; t += NT) sm[SM_W1 + t] = W1g[t];
    // W2 permuted: slot [u][4c+k] <- W2[j][2c + (k&1)],
    // j = j0 + 4*(k>>1), j0 = 4*(((4u)&63)>>1) + ((4u)>>6)
    for (int t = tid; t < 64 * 128; t += NT) {
        int u = t >> 7, p = t & 127, c = p >> 2, k = p & 3;
        int j0 = 4 * (((4 * u) & 63) >> 1) + ((4 * u) >> 6);
        int j = j0 + 4 * (k >> 1);
        sm[SM_W2P + t] = W2g[j * Ec + 2 * c + (k & 1)];
    }
    if (tid < EHc) sm[SM_B1 + tid] = b1g[tid];
    if (tid < Ec)  sm[SM_B2 + tid] = b2g[tid];
    if (tid < Lc)  sm[SM_TS + tid] = tsg[tid];

    // per-pair chain metadata (rows A=2p, B=2p+1 of this warp)
    float4 x0p[NPS];
    int obA[NPS], obB[NPS], idxA[NPS], idxB[NPS];
    unsigned actAm = 0, actBm = 0;
#pragma unroll
    for (int p = 0; p < NPS; ++p) {
        int sA = 2 * p, sB = 2 * p + 1;
        bool aA = sA < aw, aB = sB < aw;
        int qA = qstart + rowbase + (aA ? sA : 0);
        int qB = qstart + rowbase + (aB ? sB : 0);
        idxA[p] = qA >> 6; idxB[p] = qB >> 6;
        int bA = (qA >> 3) & 7, hA = qA & 7;
        int bB = (qB >> 3) & 7, hB = qB & 7;
        float2 xA = *(const float2*)&x[((bA * Lc + idxA[p]) * Hc + hA) * Ec + 2 * cg];
        float2 xB = *(const float2*)&x[((bB * Lc + idxB[p]) * Hc + hB) * Ec + 2 * cg];
        x0p[p] = make_float4(xA.x, xA.y, xB.x, xB.y);
        obA[p] = bA * (Lc * Lc * Hc * Ec * 2) + idxA[p] * (Lc * Hc * Ec * 2) +
                 hA * (Ec * 2) + 4 * cg;
        obB[p] = bB * (Lc * Lc * Hc * Ec * 2) + idxB[p] * (Lc * Hc * Ec * 2) +
                 hB * (Ec * 2) + 4 * cg;
        if (aA) actAm |= 1u << p;
        if (aB) actBm |= 1u << p;
        *(float4*)&sm[SM_Y + (pb + p) * YP + 4 * cg] =
            make_float4(xA.x, xB.x, xA.y, xB.y);
        if (aA)
            *(float4*)&out[obA[p] + idxA[p] * (Hc * Ec * 2)] =
                make_float4(xA.x, xA.x, xA.y, xA.y);
        if (aB)
            *(float4*)&out[obB[p] + idxB[p] * (Hc * Ec * 2)] =
                make_float4(xB.x, xB.x, xB.y, xB.y);
    }
    __syncthreads();   // weights visible; warps free-run after this

    const float* ts = sm + SM_TS;

    // 95 lockstep RK4 steps: fwd k < nf = 95-idx (emit j=s+1), reset to x0,
    // then bwd (dt<0, emit j=s-1). All rows warp-private -> __syncwarp only.
    for (int k = 0; k < Lc - 1; ++k) {
        ull dp[NPS];
        int joA[NPS], joB[NPS];
        unsigned rstAm = 0, rstBm = 0;
#pragma unroll
        for (int p = 0; p < NPS; ++p) {
            float dA, dB; int jA, jB;
            {
                int idx = idxA[p], nf = (Lc - 1) - idx;
                if (k < nf) {
                    int s = idx + k;
                    dA = ts[s + 1] - ts[s]; jA = s + 1;
                    if (k + 1 == nf) rstAm |= 1u << p;
                } else {
                    int s = idx - (k - nf);
                    dA = ts[s - 1] - ts[s]; jA = s - 1;
                }
            }
            {
                int idx = idxB[p], nf = (Lc - 1) - idx;
                if (k < nf) {
                    int s = idx + k;
                    dB = ts[s + 1] - ts[s]; jB = s + 1;
                    if (k + 1 == nf) rstBm |= 1u << p;
                } else {
                    int s = idx - (k - nf);
                    dB = ts[s - 1] - ts[s]; jB = s - 1;
                }
            }
            dp[p] = pk2(dA, dB);
            joA[p] = obA[p] + jA * (Hc * Ec * 2);
            joB[p] = obB[p] + jB * (Hc * Ec * 2);
        }

        gemm1(sm, SM_Y, cg, pb);
        __syncwarp();
        gemm2_epi<0>(sm, cg, pb, dp, x0p, joA, joB, rstAm, rstBm, actAm, actBm, out);
        __syncwarp();
        gemm1(sm, SM_YIN, cg, pb);
        __syncwarp();
        gemm2_epi<1>(sm, cg, pb, dp, x0p, joA, joB, rstAm, rstBm, actAm, actBm, out);
        __syncwarp();
        gemm1(sm, SM_YIN, cg, pb);
        __syncwarp();
        gemm2_epi<2>(sm, cg, pb, dp, x0p, joA, joB, rstAm, rstBm, actAm, actBm, out);
        __syncwarp();
        gemm1(sm, SM_YIN, cg, pb);
        __syncwarp();
        gemm2_epi<3>(sm, cg, pb, dp, x0p, joA, joB, rstAm, rstBm, actAm, actBm, out);
        __syncwarp();
    }
}

extern "C" void kernel_launch(void* const* d_in, const int* in_sizes, int n_in,
                              void* d_out, int out_size) {
    const float* x   = (const float*)d_in[0];
    const float* ts  = (const float*)d_in[1];
    const float* W1  = (const float*)d_in[2];
    const float* b1  = (const float*)d_in[3];
    const float* W2  = (const float*)d_in[4];
    const float* b2  = (const float*)d_in[5];
    float* out = (float*)d_out;

    cudaFuncSetAttribute(ode_kernel, cudaFuncAttributeMaxDynamicSharedMemorySize,
                         SMEM_BYTES);
    ode_kernel<<<GRID, NT, SMEM_BYTES>>>(x, ts, W1, b1, W2, b2, out);
}